// round 14
// baseline (speedup 1.0000x reference)
#include <cuda_runtime.h>
#include <stdint.h>
#include <math.h>

#define SQ 4096
#define DM 512
#define NH 8
#define HD 64

#define QT_ROWS 128            // q rows per attention CTA (8 warps x 16)
#define NQT (SQ / QT_ROWS)     // 32 q-tiles
#define CHUNK_TILES 8          // 64-key tiles per chunk (512 keys)
#define MAX_CH 8               // max chunks per q-tile

// Scratch (allocation-free requirement -> __device__ globals)
__device__ float g_qc[SQ * DM];   // tf32-rounded inputs, perm16 k-cols
__device__ float g_kc[SQ * DM];
__device__ float g_vc[SQ * DM];
__device__ float g_Wq[DM * DM];   // tf32-rounded weights, perm16 k-cols
__device__ float g_Wk[DM * DM];
__device__ float g_Wv[DM * DM];
__device__ float g_Wo[DM * DM];
__device__ float g_Q[SQ * DM];    // tf32, pre-scaled, STANDARD layout
__device__ float g_K[SQ * DM];    // tf32, perm16 on head-d dim (attn B-frags)
__device__ float g_Vt[NH * 64 * 64 * 64];  // [h][tile][col][permrow], tf32
__device__ float g_O[SQ * DM];    // attention out, tf32, perm16 k-cols
// split-K partials: chunk id = ((h*NQT + qt)*MAX_CH + c)
__device__ float g_Po[NH * NQT * MAX_CH][QT_ROWS * HD];
__device__ float g_Pm[NH * NQT * MAX_CH][QT_ROWS];
__device__ float g_Pl[NH * NQT * MAX_CH][QT_ROWS];

// ---------------------------------------------------------------------------
// helpers
// ---------------------------------------------------------------------------
__device__ __forceinline__ uint32_t f2tf(float x) {
    uint32_t u; asm("cvt.rna.tf32.f32 %0, %1;" : "=r"(u) : "f"(x)); return u;
}
__device__ __forceinline__ float f2tf_f(float x) { return __uint_as_float(f2tf(x)); }

__device__ __forceinline__ float ex2(float x) {
    float y; asm("ex2.approx.f32 %0, %1;" : "=f"(y) : "f"(x)); return y;
}

// fragment permutation: {16g+t,16g+4+t,16g+8+t,16g+12+t} -> adjacent
__device__ __forceinline__ int perm16(int k) {
    return (k & ~15) + 4 * (k & 3) + 2 * ((k >> 3) & 1) + ((k >> 2) & 1);
}

__device__ __forceinline__ void cp16(void* smem, const void* g) {
    uint32_t sa = (uint32_t)__cvta_generic_to_shared(smem);
    asm volatile("cp.async.ca.shared.global [%0], [%1], 16;" :: "r"(sa), "l"(g));
}
__device__ __forceinline__ void cp_commit() {
    asm volatile("cp.async.commit_group;");
}
template <int N>
__device__ __forceinline__ void cp_wait() {
    asm volatile("cp.async.wait_group %0;" :: "n"(N));
}

__device__ __forceinline__ void mma8(float c[4],
    uint32_t a0, uint32_t a1, uint32_t a2, uint32_t a3,
    uint32_t b0, uint32_t b1)
{
    asm volatile(
        "mma.sync.aligned.m16n8k8.row.col.f32.tf32.tf32.f32 "
        "{%0,%1,%2,%3},{%4,%5,%6,%7},{%8,%9},{%0,%1,%2,%3};"
        : "+f"(c[0]), "+f"(c[1]), "+f"(c[2]), "+f"(c[3])
        : "r"(a0), "r"(a1), "r"(a2), "r"(a3), "r"(b0), "r"(b1));
}

// ---------------------------------------------------------------------------
// prep: round to tf32 (rna) AND scatter columns by perm16 (k-dim layout).
// ONE launch: grid.y 0..2 = activations (n4 = 524288), 3..6 = weights (65536).
// ---------------------------------------------------------------------------
__global__ void prep_all(
    const float* __restrict__ s0, const float* __restrict__ s1,
    const float* __restrict__ s2, const float* __restrict__ s3,
    const float* __restrict__ s4, const float* __restrict__ s5,
    const float* __restrict__ s6,
    float* __restrict__ d0, float* __restrict__ d1, float* __restrict__ d2,
    float* __restrict__ d3, float* __restrict__ d4, float* __restrict__ d5,
    float* __restrict__ d6)
{
    const int y = blockIdx.y;
    int i = blockIdx.x * blockDim.x + threadIdx.x;
    const int n4 = (y < 3) ? (SQ * DM / 4) : (DM * DM / 4);
    if (i >= n4) return;
    const float* src; float* dst;
    switch (y) {
        case 0: src = s0; dst = d0; break;
        case 1: src = s1; dst = d1; break;
        case 2: src = s2; dst = d2; break;
        case 3: src = s3; dst = d3; break;
        case 4: src = s4; dst = d4; break;
        case 5: src = s5; dst = d5; break;
        default: src = s6; dst = d6; break;
    }
    float4 v = ((const float4*)src)[i];
    int row = i >> 7;                 // 128 float4 per 512-col row
    int j   = i & 127;
    int base = row * DM + ((4 * j) & ~15) + 2 * ((j >> 1) & 1) + (j & 1);
    dst[base +  0] = f2tf_f(v.x);
    dst[base +  4] = f2tf_f(v.y);
    dst[base +  8] = f2tf_f(v.z);
    dst[base + 12] = f2tf_f(v.w);
}

// ---------------------------------------------------------------------------
// Projection GEMM core: 64x64 tile, BK=32, THREE-stage cp.async ring
// (prefetch distance 2 -> ~1000cyc to cover load latency), 128 threads.
// A and W perm16 on k-dim -> one LDS.128 per operand feeds TWO k8 mmas.
// smem stride 48 floats (conflict-free LDS.128). Epilogue layout by MODE:
//   0 = standard, no cvt (final out)
//   1 = standard, cvt (+oscale)            (Q)
//   2 = perm16 on head-d columns, cvt      (K)
//   3 = transposed+permrow into g_Vt, cvt  (V)
// ---------------------------------------------------------------------------
#define PST 48
#define PSTAGE (64 * PST)     // 3072 floats per stage per matrix
#define PSTAGES 3

template <int MODE>
__device__ __forceinline__ void proj_body(
    float* __restrict__ As, float* __restrict__ Ws,
    const float* __restrict__ A, const float* __restrict__ W,
    const float* __restrict__ bias, float* __restrict__ C, float oscale)
{
    const int tid  = threadIdx.x;
    const int warp = tid >> 5, lane = tid & 31;
    const int gid  = lane >> 2, tig = lane & 3;
    const int m0 = blockIdx.y * 64, n0 = blockIdx.x * 64;

    const int r  = tid >> 3;
    const int c4 = tid & 7;

    float acc[8][4] = {};

    // prologue: prefetch k-slabs 0 and 1 into stages 0,1
    #pragma unroll
    for (int st = 0; st < 2; st++) {
        int k0 = st * 32;
        #pragma unroll
        for (int i = 0; i < 4; i++) {
            int rr = r + 16 * i;
            cp16(&As[st * PSTAGE + rr * PST + c4 * 4], &A[(m0 + rr) * DM + k0 + c4 * 4]);
            cp16(&Ws[st * PSTAGE + rr * PST + c4 * 4], &W[(n0 + rr) * DM + k0 + c4 * 4]);
        }
        cp_commit();
    }

    for (int kk = 0; kk < 16; kk++) {
        if (kk + 2 < 16) {
            int k0n = (kk + 2) * 32, sn = (kk + 2) % PSTAGES;
            #pragma unroll
            for (int i = 0; i < 4; i++) {
                int rr = r + 16 * i;
                cp16(&As[sn * PSTAGE + rr * PST + c4 * 4], &A[(m0 + rr) * DM + k0n + c4 * 4]);
                cp16(&Ws[sn * PSTAGE + rr * PST + c4 * 4], &W[(n0 + rr) * DM + k0n + c4 * 4]);
            }
            cp_commit();
            cp_wait<2>();
        } else if (kk == 14) {
            cp_wait<1>();
        } else {
            cp_wait<0>();
        }
        __syncthreads();

        const int s = kk % PSTAGES;
        const float* ab  = &As[s * PSTAGE + (warp * 16 + gid) * PST];
        const float* ab8 = ab + 8 * PST;
        const float* wb  = &Ws[s * PSTAGE + gid * PST];
        #pragma unroll
        for (int pair = 0; pair < 2; pair++) {
            float4 fa  = *(const float4*)&ab [pair * 16 + 4 * tig];
            float4 fa2 = *(const float4*)&ab8[pair * 16 + 4 * tig];
            #pragma unroll
            for (int nt = 0; nt < 8; nt++) {
                float4 fb = *(const float4*)&wb[nt * 8 * PST + pair * 16 + 4 * tig];
                mma8(acc[nt],
                     __float_as_uint(fa.x), __float_as_uint(fa2.x),
                     __float_as_uint(fa.y), __float_as_uint(fa2.y),
                     __float_as_uint(fb.x), __float_as_uint(fb.y));
                mma8(acc[nt],
                     __float_as_uint(fa.z), __float_as_uint(fa2.z),
                     __float_as_uint(fa.w), __float_as_uint(fa2.w),
                     __float_as_uint(fb.z), __float_as_uint(fb.w));
            }
        }
        __syncthreads();
    }

    const int r0 = m0 + warp * 16 + gid;
    #pragma unroll
    for (int nt = 0; nt < 8; nt++) {
        int n = n0 + nt * 8 + 2 * tig;
        float2 b2 = *(const float2*)&bias[n];
        float v00 = (acc[nt][0] + b2.x) * oscale;
        float v01 = (acc[nt][1] + b2.y) * oscale;
        float v10 = (acc[nt][2] + b2.x) * oscale;
        float v11 = (acc[nt][3] + b2.y) * oscale;
        if (MODE >= 1) {
            v00 = f2tf_f(v00); v01 = f2tf_f(v01);
            v10 = f2tf_f(v10); v11 = f2tf_f(v11);
        }
        if (MODE <= 1) {
            *(float2*)&C[r0 * DM + n]       = make_float2(v00, v01);
            *(float2*)&C[(r0 + 8) * DM + n] = make_float2(v10, v11);
        } else if (MODE == 2) {
            // K: permute within the head-local d dimension (attn B-frags)
            int p0 = (n & ~63) + perm16(n & 63);
            int p1 = (n & ~63) + perm16((n + 1) & 63);
            C[r0 * DM + p0]       = v00;
            C[r0 * DM + p1]       = v01;
            C[(r0 + 8) * DM + p0] = v10;
            C[(r0 + 8) * DM + p1] = v11;
        } else {
            // V: transposed + permrow -> g_Vt[h][tile][col][permrow]
            int h0 = n >> 6, c0 = n & 63, c1 = (n + 1) & 63;
            int tl = r0 >> 6;
            int u0 = perm16(r0 & 63), u1 = perm16((r0 + 8) & 63);
            float* base = C + (h0 * 64 + tl) * 4096;
            base[c0 * 64 + u0] = v00;
            base[c1 * 64 + u0] = v01;
            base[c0 * 64 + u1] = v10;
            base[c1 * 64 + u1] = v11;
        }
    }
}

#define PROJ_SMEM_BYTES (2 * PSTAGES * PSTAGE * 4)   // 73728 B

__global__ __launch_bounds__(128, 3) void proj_qkv(
    const float* __restrict__ bq, const float* __restrict__ bk,
    const float* __restrict__ bv, float qscale)
{
    extern __shared__ float pdyn[];
    float* As = pdyn;
    float* Ws = pdyn + PSTAGES * PSTAGE;
    if (blockIdx.z == 0)      proj_body<1>(As, Ws, g_qc, g_Wq, bq, g_Q, qscale);
    else if (blockIdx.z == 1) proj_body<2>(As, Ws, g_kc, g_Wk, bk, g_K, 1.f);
    else                      proj_body<3>(As, Ws, g_vc, g_Wv, bv, g_Vt, 1.f);
}

__global__ __launch_bounds__(128, 3) void proj_out(
    const float* __restrict__ bo, float* __restrict__ C)
{
    extern __shared__ float pdyn[];
    float* As = pdyn;
    float* Ws = pdyn + PSTAGES * PSTAGE;
    proj_body<0>(As, Ws, g_O, g_Wo, bo, C, 1.f);
}

// ---------------------------------------------------------------------------
// Split-K flash attention: 256 threads, 128 q-rows per CTA, 64-key tiles,
// chunks of <=8 tiles (fine quanta -> good wave balance).
// K/V fragment-permuted -> every B operand pair is ONE LDS.128.
// ---------------------------------------------------------------------------
#define KV_STRIDE 80
#define KS_ELEMS (64 * KV_STRIDE)
#define VS_ELEMS (64 * KV_STRIDE)
#define ATTN_SMEM_BYTES ((2 * KS_ELEMS + 2 * VS_ELEMS) * 4)

__global__ __launch_bounds__(256, 2) void attn_tc()
{
    const int qt = NQT - 1 - blockIdx.y;
    const int ch = blockIdx.x;
    const int NTtot = 2 * qt + 2;
    const int t0 = ch * CHUNK_TILES;
    if (t0 >= NTtot) return;
    const int t1 = min(t0 + CHUNK_TILES, NTtot);

    extern __shared__ float dyn[];
    float* Ks = dyn;
    float* Vs = dyn + 2 * KS_ELEMS;

    const int h  = blockIdx.z;
    const int tid  = threadIdx.x;
    const int warp = tid >> 5, lane = tid & 31;
    const int gid  = lane >> 2, tig = lane & 3;

    uint32_t qa[8][4];
    const float* Qp = g_Q + (qt * QT_ROWS + warp * 16) * DM + h * HD;
    #pragma unroll
    for (int ds = 0; ds < 8; ds++) {
        qa[ds][0] = __float_as_uint(Qp[gid * DM       + ds * 8 + tig    ]);
        qa[ds][1] = __float_as_uint(Qp[(gid + 8) * DM + ds * 8 + tig    ]);
        qa[ds][2] = __float_as_uint(Qp[gid * DM       + ds * 8 + tig + 4]);
        qa[ds][3] = __float_as_uint(Qp[(gid + 8) * DM + ds * 8 + tig + 4]);
    }

    float o[8][4] = {};
    float mr0 = -1e30f, mr1 = -1e30f;
    float ls0 = 0.f, ls1 = 0.f;

    const int s0l = (lane & ~3) | (tig >> 1);
    const int s2l = s0l + 2;

    const int crow = tid >> 4;
    const int cc4  = tid & 15;

    {
        const float* kp = g_K + (t0 * 64) * DM + h * HD;
        const float* vp = g_Vt + (h * 64 + t0) * 4096;
        #pragma unroll
        for (int i = 0; i < 4; i++) {
            int rr = crow + 16 * i;
            cp16(&Ks[rr * KV_STRIDE + cc4 * 4], &kp[rr * DM + cc4 * 4]);
            cp16(&Vs[rr * KV_STRIDE + cc4 * 4], &vp[rr * 64 + cc4 * 4]);
        }
        cp_commit();
    }

    for (int t = t0; t < t1; t++) {
        if (t + 1 < t1) {
            int sn = (t + 1) & 1;
            const float* kp = g_K + ((t + 1) * 64) * DM + h * HD;
            const float* vp = g_Vt + (h * 64 + (t + 1)) * 4096;
            #pragma unroll
            for (int i = 0; i < 4; i++) {
                int rr = crow + 16 * i;
                cp16(&Ks[sn * KS_ELEMS + rr * KV_STRIDE + cc4 * 4], &kp[rr * DM + cc4 * 4]);
                cp16(&Vs[sn * VS_ELEMS + rr * KV_STRIDE + cc4 * 4], &vp[rr * 64 + cc4 * 4]);
            }
            cp_commit();
            cp_wait<1>();
        } else {
            cp_wait<0>();
        }
        __syncthreads();

        const float* ks = Ks + (t & 1) * KS_ELEMS;
        const float* vs = Vs + (t & 1) * VS_ELEMS;

        float sc4[8][4] = {};
        #pragma unroll
        for (int g = 0; g < 4; g++) {
            #pragma unroll
            for (int nt = 0; nt < 8; nt++) {
                float4 w = *(const float4*)&ks[(nt * 8 + gid) * KV_STRIDE + 16 * g + 4 * tig];
                mma8(sc4[nt], qa[2*g][0], qa[2*g][1], qa[2*g][2], qa[2*g][3],
                     __float_as_uint(w.x), __float_as_uint(w.y));
                mma8(sc4[nt], qa[2*g+1][0], qa[2*g+1][1], qa[2*g+1][2], qa[2*g+1][3],
                     __float_as_uint(w.z), __float_as_uint(w.w));
            }
        }

        if (t >= 2 * qt) {
            int ql0 = qt * QT_ROWS + warp * 16 + gid, ql1 = ql0 + 8;
            int kb0 = t * 64;
            #pragma unroll
            for (int nt = 0; nt < 8; nt++) {
                int kc = kb0 + nt * 8 + 2 * tig;
                if (kc     > ql0) sc4[nt][0] = -1e30f;
                if (kc + 1 > ql0) sc4[nt][1] = -1e30f;
                if (kc     > ql1) sc4[nt][2] = -1e30f;
                if (kc + 1 > ql1) sc4[nt][3] = -1e30f;
            }
        }

        float tm0 = -1e30f, tm1 = -1e30f;
        #pragma unroll
        for (int nt = 0; nt < 8; nt++) {
            tm0 = fmaxf(tm0, fmaxf(sc4[nt][0], sc4[nt][1]));
            tm1 = fmaxf(tm1, fmaxf(sc4[nt][2], sc4[nt][3]));
        }
        tm0 = fmaxf(tm0, __shfl_xor_sync(0xffffffffu, tm0, 1));
        tm0 = fmaxf(tm0, __shfl_xor_sync(0xffffffffu, tm0, 2));
        tm1 = fmaxf(tm1, __shfl_xor_sync(0xffffffffu, tm1, 1));
        tm1 = fmaxf(tm1, __shfl_xor_sync(0xffffffffu, tm1, 2));

        float mn0 = fmaxf(fmaxf(mr0, tm0), -1e28f);
        float mn1 = fmaxf(fmaxf(mr1, tm1), -1e28f);
        float rs0 = ex2(mr0 - mn0), rs1 = ex2(mr1 - mn1);
        mr0 = mn0; mr1 = mn1;

        uint32_t pu[8][4];
        float a0s = 0.f, a1s = 0.f;
        #pragma unroll
        for (int nt = 0; nt < 8; nt++) {
            float p0 = ex2(sc4[nt][0] - mn0);
            float p1 = ex2(sc4[nt][1] - mn0);
            float p2 = ex2(sc4[nt][2] - mn1);
            float p3 = ex2(sc4[nt][3] - mn1);
            a0s += p0 + p1; a1s += p2 + p3;
            pu[nt][0] = f2tf(p0); pu[nt][1] = f2tf(p1);
            pu[nt][2] = f2tf(p2); pu[nt][3] = f2tf(p3);
        }
        ls0 = ls0 * rs0 + a0s;
        ls1 = ls1 * rs1 + a1s;

        #pragma unroll
        for (int nt = 0; nt < 8; nt++) {
            o[nt][0] *= rs0; o[nt][1] *= rs0;
            o[nt][2] *= rs1; o[nt][3] *= rs1;
        }

        #pragma unroll
        for (int g = 0; g < 4; g++) {
            uint32_t A0[2], A1[2], A2[2], A3[2];
            #pragma unroll
            for (int qq = 0; qq < 2; qq++) {
                int kt = 2 * g + qq;
                uint32_t u0, u1, u2, u3;
                u0 = __shfl_sync(0xffffffffu, pu[kt][0], s0l);
                u1 = __shfl_sync(0xffffffffu, pu[kt][1], s0l);
                A0[qq] = (tig & 1) ? u1 : u0;
                u2 = __shfl_sync(0xffffffffu, pu[kt][2], s0l);
                u3 = __shfl_sync(0xffffffffu, pu[kt][3], s0l);
                A1[qq] = (tig & 1) ? u3 : u2;
                u0 = __shfl_sync(0xffffffffu, pu[kt][0], s2l);
                u1 = __shfl_sync(0xffffffffu, pu[kt][1], s2l);
                A2[qq] = (tig & 1) ? u1 : u0;
                u2 = __shfl_sync(0xffffffffu, pu[kt][2], s2l);
                u3 = __shfl_sync(0xffffffffu, pu[kt][3], s2l);
                A3[qq] = (tig & 1) ? u3 : u2;
            }
            #pragma unroll
            for (int nt = 0; nt < 8; nt++) {
                float4 w = *(const float4*)&vs[(nt * 8 + gid) * KV_STRIDE + 16 * g + 4 * tig];
                mma8(o[nt], A0[0], A1[0], A2[0], A3[0],
                     __float_as_uint(w.x), __float_as_uint(w.y));
                mma8(o[nt], A0[1], A1[1], A2[1], A3[1],
                     __float_as_uint(w.z), __float_as_uint(w.w));
            }
        }
        __syncthreads();
    }

    ls0 += __shfl_xor_sync(0xffffffffu, ls0, 1);
    ls0 += __shfl_xor_sync(0xffffffffu, ls0, 2);
    ls1 += __shfl_xor_sync(0xffffffffu, ls1, 1);
    ls1 += __shfl_xor_sync(0xffffffffu, ls1, 2);

    const int cid = (h * NQT + qt) * MAX_CH + ch;
    const int r0 = warp * 16 + gid, r1 = r0 + 8;
    float* Pop = g_Po[cid];
    #pragma unroll
    for (int nt = 0; nt < 8; nt++) {
        int c = nt * 8 + 2 * tig;
        *(float2*)&Pop[r0 * HD + c] = make_float2(o[nt][0], o[nt][1]);
        *(float2*)&Pop[r1 * HD + c] = make_float2(o[nt][2], o[nt][3]);
    }
    if (tig == 0) {
        g_Pm[cid][r0] = mr0; g_Pm[cid][r1] = mr1;
        g_Pl[cid][r0] = ls0; g_Pl[cid][r1] = ls1;
    }
}

// ---------------------------------------------------------------------------
// Split-K reduce (parallel): grid (NQT, NH, 4); each block = 32 rows,
// each thread = 1 row x 8 cols (two independent float4 chains per chunk).
// ---------------------------------------------------------------------------
__global__ __launch_bounds__(256) void attn_reduce()
{
    const int qt = blockIdx.x, h = blockIdx.y;
    const int nch = min(MAX_CH, (2 * qt + 2 + CHUNK_TILES - 1) / CHUNK_TILES);
    const int tid = threadIdx.x;
    const int row = blockIdx.z * 32 + (tid >> 3);   // 32 rows per block
    const int c0  = (tid & 7) * 8;                  // 8 cols per thread
    const int cidb = (h * NQT + qt) * MAX_CH;

    float m[MAX_CH], l[MAX_CH];
    float M = -1e30f;
    for (int c = 0; c < nch; c++) {
        m[c] = g_Pm[cidb + c][row];
        l[c] = g_Pl[cidb + c][row];
        M = fmaxf(M, m[c]);
    }
    float w[MAX_CH];
    float L = 0.f;
    for (int c = 0; c < nch; c++) {
        w[c] = ex2(m[c] - M);
        L += l[c] * w[c];
    }
    float inv = 1.f / L;

    float4 a0 = make_float4(0.f, 0.f, 0.f, 0.f);
    float4 a1 = make_float4(0.f, 0.f, 0.f, 0.f);
    for (int c = 0; c < nch; c++) {
        const float* p = &g_Po[cidb + c][row * HD + c0];
        float4 v0 = *(const float4*)&p[0];
        float4 v1 = *(const float4*)&p[4];
        float wc = w[c];
        a0.x += v0.x * wc; a0.y += v0.y * wc;
        a0.z += v0.z * wc; a0.w += v0.w * wc;
        a1.x += v1.x * wc; a1.y += v1.y * wc;
        a1.z += v1.z * wc; a1.w += v1.w * wc;
    }

    // g_O is perm16 on the k-dim: global col gc (mult of 4) -> base+{0,4,8,12}
    float* Orow = g_O + (qt * QT_ROWS + row) * DM;
    int gc = h * HD + c0;                 // multiple of 8
    int b0 = perm16(gc);
    int b1 = perm16(gc + 4);
    Orow[b0 +  0] = f2tf_f(a0.x * inv);
    Orow[b0 +  4] = f2tf_f(a0.y * inv);
    Orow[b0 +  8] = f2tf_f(a0.z * inv);
    Orow[b0 + 12] = f2tf_f(a0.w * inv);
    Orow[b1 +  0] = f2tf_f(a1.x * inv);
    Orow[b1 +  4] = f2tf_f(a1.y * inv);
    Orow[b1 +  8] = f2tf_f(a1.z * inv);
    Orow[b1 + 12] = f2tf_f(a1.w * inv);
}

// ---------------------------------------------------------------------------
// kernel_launch
// Input order: q, k, v, padding_mask, Wq, bq, Wk, bk, Wv, bv, Wo, bo
// ---------------------------------------------------------------------------
extern "C" void kernel_launch(void* const* d_in, const int* in_sizes, int n_in,
                              void* d_out, int out_size)
{
    (void)in_sizes; (void)n_in; (void)out_size;
    const float* q  = (const float*)d_in[0];
    const float* k  = (const float*)d_in[1];
    const float* v  = (const float*)d_in[2];
    const float* Wq = (const float*)d_in[4];
    const float* bq = (const float*)d_in[5];
    const float* Wk = (const float*)d_in[6];
    const float* bk = (const float*)d_in[7];
    const float* Wv = (const float*)d_in[8];
    const float* bv = (const float*)d_in[9];
    const float* Wo = (const float*)d_in[10];
    const float* bo = (const float*)d_in[11];
    float* out = (float*)d_out;

    float *qc, *kc, *vc, *wq, *wk, *wv, *wo;
    cudaGetSymbolAddress((void**)&qc, g_qc);
    cudaGetSymbolAddress((void**)&kc, g_kc);
    cudaGetSymbolAddress((void**)&vc, g_vc);
    cudaGetSymbolAddress((void**)&wq, g_Wq);
    cudaGetSymbolAddress((void**)&wk, g_Wk);
    cudaGetSymbolAddress((void**)&wv, g_Wv);
    cudaGetSymbolAddress((void**)&wo, g_Wo);

    static int smem_set = 0;
    if (!smem_set) {
        cudaFuncSetAttribute(attn_tc,
            cudaFuncAttributeMaxDynamicSharedMemorySize, ATTN_SMEM_BYTES);
        cudaFuncSetAttribute(proj_qkv,
            cudaFuncAttributeMaxDynamicSharedMemorySize, PROJ_SMEM_BYTES);
        cudaFuncSetAttribute(proj_out,
            cudaFuncAttributeMaxDynamicSharedMemorySize, PROJ_SMEM_BYTES);
        smem_set = 1;
    }

    const int n4i = SQ * DM / 4;      // 524288 -> 2048 blocks of 256
    dim3 pg(n4i / 256, 7);
    prep_all<<<pg, 256>>>(q, k, v, Wq, Wk, Wv, Wo,
                          qc, kc, vc, wq, wk, wv, wo);

    const float QSCALE = 0.125f * 1.4426950408889634f;
    dim3 pgrid(DM / 64, SQ / 64, 3);
    proj_qkv<<<pgrid, 128, PROJ_SMEM_BYTES>>>(bq, bk, bv, QSCALE);

    dim3 agrid(MAX_CH, NQT, NH);       // (8, 32, 8)
    attn_tc<<<agrid, 256, ATTN_SMEM_BYTES>>>();

    dim3 rgrid(NQT, NH, 4);            // (32, 8, 4) = 1024 CTAs
    attn_reduce<<<rgrid, 256>>>();

    dim3 ogrid(DM / 64, SQ / 64);
    proj_out<<<ogrid, 128, PROJ_SMEM_BYTES>>>(bo, out);
}

// round 16
// speedup vs baseline: 1.1424x; 1.1424x over previous
#include <cuda_runtime.h>
#include <stdint.h>
#include <math.h>

#define SQ 4096
#define DM 512
#define NH 8
#define HD 64

#define QT_ROWS 128            // q rows per attention CTA (8 warps x 16)
#define NQT (SQ / QT_ROWS)     // 32 q-tiles
#define CHUNK_TILES 8          // 64-key tiles per chunk (512 keys)
#define MAX_CH 8               // max chunks per q-tile

// Scratch (allocation-free requirement -> __device__ globals)
__device__ float g_qc[SQ * DM];   // tf32-rounded inputs, perm16 k-cols
__device__ float g_kc[SQ * DM];
__device__ float g_vc[SQ * DM];
__device__ float g_Wq[DM * DM];   // tf32-rounded weights, perm16 k-cols
__device__ float g_Wk[DM * DM];
__device__ float g_Wv[DM * DM];
__device__ float g_Wo[DM * DM];
__device__ float g_Q[SQ * DM];    // tf32, pre-scaled, STANDARD layout
__device__ float g_K[SQ * DM];    // tf32, perm16 on head-d dim (attn B-frags)
__device__ float g_Vt[NH * 64 * 64 * 64];  // [h][tile][col][permrow], tf32
__device__ float g_O[SQ * DM];    // attention out, tf32, perm16 k-cols
// split-K partials: chunk id = ((h*NQT + qt)*MAX_CH + c)
__device__ float g_Po[NH * NQT * MAX_CH][QT_ROWS * HD];
__device__ float g_Pm[NH * NQT * MAX_CH][QT_ROWS];
__device__ float g_Pl[NH * NQT * MAX_CH][QT_ROWS];

// ---------------------------------------------------------------------------
// helpers
// ---------------------------------------------------------------------------
__device__ __forceinline__ uint32_t f2tf(float x) {
    uint32_t u; asm("cvt.rna.tf32.f32 %0, %1;" : "=r"(u) : "f"(x)); return u;
}
__device__ __forceinline__ float f2tf_f(float x) { return __uint_as_float(f2tf(x)); }

__device__ __forceinline__ float ex2(float x) {
    float y; asm("ex2.approx.f32 %0, %1;" : "=f"(y) : "f"(x)); return y;
}

// fragment permutation: {16g+t,16g+4+t,16g+8+t,16g+12+t} -> adjacent
__device__ __forceinline__ int perm16(int k) {
    return (k & ~15) + 4 * (k & 3) + 2 * ((k >> 3) & 1) + ((k >> 2) & 1);
}

// cp.async with L2-only caching (.cg): smem is the destination, L1
// allocation is pure overhead on the L1tex pipe the attn loop saturates.
__device__ __forceinline__ void cp16(void* smem, const void* g) {
    uint32_t sa = (uint32_t)__cvta_generic_to_shared(smem);
    asm volatile("cp.async.cg.shared.global [%0], [%1], 16;" :: "r"(sa), "l"(g));
}
__device__ __forceinline__ void cp_commit() {
    asm volatile("cp.async.commit_group;");
}
template <int N>
__device__ __forceinline__ void cp_wait() {
    asm volatile("cp.async.wait_group %0;" :: "n"(N));
}

__device__ __forceinline__ void mma8(float c[4],
    uint32_t a0, uint32_t a1, uint32_t a2, uint32_t a3,
    uint32_t b0, uint32_t b1)
{
    asm volatile(
        "mma.sync.aligned.m16n8k8.row.col.f32.tf32.tf32.f32 "
        "{%0,%1,%2,%3},{%4,%5,%6,%7},{%8,%9},{%0,%1,%2,%3};"
        : "+f"(c[0]), "+f"(c[1]), "+f"(c[2]), "+f"(c[3])
        : "r"(a0), "r"(a1), "r"(a2), "r"(a3), "r"(b0), "r"(b1));
}

// ---------------------------------------------------------------------------
// prep: round to tf32 (rna) AND scatter columns by perm16 (k-dim layout).
// ONE launch: grid.y 0..2 = activations (n4 = 524288), 3..6 = weights (65536).
// ---------------------------------------------------------------------------
__global__ void prep_all(
    const float* __restrict__ s0, const float* __restrict__ s1,
    const float* __restrict__ s2, const float* __restrict__ s3,
    const float* __restrict__ s4, const float* __restrict__ s5,
    const float* __restrict__ s6,
    float* __restrict__ d0, float* __restrict__ d1, float* __restrict__ d2,
    float* __restrict__ d3, float* __restrict__ d4, float* __restrict__ d5,
    float* __restrict__ d6)
{
    const int y = blockIdx.y;
    int i = blockIdx.x * blockDim.x + threadIdx.x;
    const int n4 = (y < 3) ? (SQ * DM / 4) : (DM * DM / 4);
    if (i >= n4) return;
    const float* src; float* dst;
    switch (y) {
        case 0: src = s0; dst = d0; break;
        case 1: src = s1; dst = d1; break;
        case 2: src = s2; dst = d2; break;
        case 3: src = s3; dst = d3; break;
        case 4: src = s4; dst = d4; break;
        case 5: src = s5; dst = d5; break;
        default: src = s6; dst = d6; break;
    }
    float4 v = ((const float4*)src)[i];
    int row = i >> 7;                 // 128 float4 per 512-col row
    int j   = i & 127;
    int base = row * DM + ((4 * j) & ~15) + 2 * ((j >> 1) & 1) + (j & 1);
    dst[base +  0] = f2tf_f(v.x);
    dst[base +  4] = f2tf_f(v.y);
    dst[base +  8] = f2tf_f(v.z);
    dst[base + 12] = f2tf_f(v.w);
}

// ---------------------------------------------------------------------------
// Projection GEMM core (R13 config: 2-stage ring, 4 CTAs/SM): 64x64 tile,
// BK=32, 128 threads. A and W perm16 on k-dim -> one LDS.128 per operand
// feeds TWO k8 mmas. smem stride 48 floats (conflict-free LDS.128).
// Epilogue layout by MODE:
//   0 = standard, no cvt (final out)
//   1 = standard, cvt (+oscale)            (Q)
//   2 = perm16 on head-d columns, cvt      (K)
//   3 = transposed+permrow into g_Vt, cvt  (V)
// ---------------------------------------------------------------------------
#define PST 48
#define PSTAGE (64 * PST)     // 3072 floats per stage per matrix

template <int MODE>
__device__ __forceinline__ void proj_body(
    float* __restrict__ As, float* __restrict__ Ws,
    const float* __restrict__ A, const float* __restrict__ W,
    const float* __restrict__ bias, float* __restrict__ C, float oscale)
{
    const int tid  = threadIdx.x;
    const int warp = tid >> 5, lane = tid & 31;
    const int gid  = lane >> 2, tig = lane & 3;
    const int m0 = blockIdx.y * 64, n0 = blockIdx.x * 64;

    const int r  = tid >> 3;
    const int c4 = tid & 7;

    float acc[8][4] = {};

    #pragma unroll
    for (int i = 0; i < 4; i++) {
        int rr = r + 16 * i;
        cp16(&As[rr * PST + c4 * 4], &A[(m0 + rr) * DM + c4 * 4]);
        cp16(&Ws[rr * PST + c4 * 4], &W[(n0 + rr) * DM + c4 * 4]);
    }
    cp_commit();

    for (int kk = 0; kk < 16; kk++) {
        if (kk < 15) {
            int k0n = (kk + 1) * 32, sn = (kk + 1) & 1;
            #pragma unroll
            for (int i = 0; i < 4; i++) {
                int rr = r + 16 * i;
                cp16(&As[sn * PSTAGE + rr * PST + c4 * 4], &A[(m0 + rr) * DM + k0n + c4 * 4]);
                cp16(&Ws[sn * PSTAGE + rr * PST + c4 * 4], &W[(n0 + rr) * DM + k0n + c4 * 4]);
            }
            cp_commit();
            cp_wait<1>();
        } else {
            cp_wait<0>();
        }
        __syncthreads();

        const int s = kk & 1;
        const float* ab  = &As[s * PSTAGE + (warp * 16 + gid) * PST];
        const float* ab8 = ab + 8 * PST;
        const float* wb  = &Ws[s * PSTAGE + gid * PST];
        #pragma unroll
        for (int pair = 0; pair < 2; pair++) {
            float4 fa  = *(const float4*)&ab [pair * 16 + 4 * tig];
            float4 fa2 = *(const float4*)&ab8[pair * 16 + 4 * tig];
            #pragma unroll
            for (int nt = 0; nt < 8; nt++) {
                float4 fb = *(const float4*)&wb[nt * 8 * PST + pair * 16 + 4 * tig];
                mma8(acc[nt],
                     __float_as_uint(fa.x), __float_as_uint(fa2.x),
                     __float_as_uint(fa.y), __float_as_uint(fa2.y),
                     __float_as_uint(fb.x), __float_as_uint(fb.y));
                mma8(acc[nt],
                     __float_as_uint(fa.z), __float_as_uint(fa2.z),
                     __float_as_uint(fa.w), __float_as_uint(fa2.w),
                     __float_as_uint(fb.z), __float_as_uint(fb.w));
            }
        }
        __syncthreads();
    }

    const int r0 = m0 + warp * 16 + gid;
    #pragma unroll
    for (int nt = 0; nt < 8; nt++) {
        int n = n0 + nt * 8 + 2 * tig;
        float2 b2 = *(const float2*)&bias[n];
        float v00 = (acc[nt][0] + b2.x) * oscale;
        float v01 = (acc[nt][1] + b2.y) * oscale;
        float v10 = (acc[nt][2] + b2.x) * oscale;
        float v11 = (acc[nt][3] + b2.y) * oscale;
        if (MODE >= 1) {
            v00 = f2tf_f(v00); v01 = f2tf_f(v01);
            v10 = f2tf_f(v10); v11 = f2tf_f(v11);
        }
        if (MODE <= 1) {
            *(float2*)&C[r0 * DM + n]       = make_float2(v00, v01);
            *(float2*)&C[(r0 + 8) * DM + n] = make_float2(v10, v11);
        } else if (MODE == 2) {
            // K: permute within the head-local d dimension (attn B-frags)
            int p0 = (n & ~63) + perm16(n & 63);
            int p1 = (n & ~63) + perm16((n + 1) & 63);
            C[r0 * DM + p0]       = v00;
            C[r0 * DM + p1]       = v01;
            C[(r0 + 8) * DM + p0] = v10;
            C[(r0 + 8) * DM + p1] = v11;
        } else {
            // V: transposed + permrow -> g_Vt[h][tile][col][permrow]
            int h0 = n >> 6, c0 = n & 63, c1 = (n + 1) & 63;
            int tl = r0 >> 6;
            int u0 = perm16(r0 & 63), u1 = perm16((r0 + 8) & 63);
            float* base = C + (h0 * 64 + tl) * 4096;
            base[c0 * 64 + u0] = v00;
            base[c1 * 64 + u0] = v01;
            base[c0 * 64 + u1] = v10;
            base[c1 * 64 + u1] = v11;
        }
    }
}

#define PROJ_SMEM_BYTES (4 * PSTAGE * 4)   // 2 matrices x 2 stages x 3072 f

__global__ __launch_bounds__(128, 4) void proj_qkv(
    const float* __restrict__ bq, const float* __restrict__ bk,
    const float* __restrict__ bv, float qscale)
{
    extern __shared__ float pdyn[];
    float* As = pdyn;
    float* Ws = pdyn + 2 * PSTAGE;
    if (blockIdx.z == 0)      proj_body<1>(As, Ws, g_qc, g_Wq, bq, g_Q, qscale);
    else if (blockIdx.z == 1) proj_body<2>(As, Ws, g_kc, g_Wk, bk, g_K, 1.f);
    else                      proj_body<3>(As, Ws, g_vc, g_Wv, bv, g_Vt, 1.f);
}

__global__ __launch_bounds__(128, 4) void proj_out(
    const float* __restrict__ bo, float* __restrict__ C)
{
    extern __shared__ float pdyn[];
    float* As = pdyn;
    float* Ws = pdyn + 2 * PSTAGE;
    proj_body<0>(As, Ws, g_O, g_Wo, bo, C, 1.f);
}

// ---------------------------------------------------------------------------
// Split-K flash attention: 256 threads, 128 q-rows per CTA, 64-key tiles,
// chunks of <=8 tiles (fine quanta -> good wave balance).
// K/V fragment-permuted -> every B operand pair is ONE LDS.128.
// ---------------------------------------------------------------------------
#define KV_STRIDE 80
#define KS_ELEMS (64 * KV_STRIDE)
#define VS_ELEMS (64 * KV_STRIDE)
#define ATTN_SMEM_BYTES ((2 * KS_ELEMS + 2 * VS_ELEMS) * 4)

__global__ __launch_bounds__(256, 2) void attn_tc()
{
    const int qt = NQT - 1 - blockIdx.y;
    const int ch = blockIdx.x;
    const int NTtot = 2 * qt + 2;
    const int t0 = ch * CHUNK_TILES;
    if (t0 >= NTtot) return;
    const int t1 = min(t0 + CHUNK_TILES, NTtot);

    extern __shared__ float dyn[];
    float* Ks = dyn;
    float* Vs = dyn + 2 * KS_ELEMS;

    const int h  = blockIdx.z;
    const int tid  = threadIdx.x;
    const int warp = tid >> 5, lane = tid & 31;
    const int gid  = lane >> 2, tig = lane & 3;

    uint32_t qa[8][4];
    const float* Qp = g_Q + (qt * QT_ROWS + warp * 16) * DM + h * HD;
    #pragma unroll
    for (int ds = 0; ds < 8; ds++) {
        qa[ds][0] = __float_as_uint(Qp[gid * DM       + ds * 8 + tig    ]);
        qa[ds][1] = __float_as_uint(Qp[(gid + 8) * DM + ds * 8 + tig    ]);
        qa[ds][2] = __float_as_uint(Qp[gid * DM       + ds * 8 + tig + 4]);
        qa[ds][3] = __float_as_uint(Qp[(gid + 8) * DM + ds * 8 + tig + 4]);
    }

    float o[8][4] = {};
    float mr0 = -1e30f, mr1 = -1e30f;
    float ls0 = 0.f, ls1 = 0.f;

    const int s0l = (lane & ~3) | (tig >> 1);
    const int s2l = s0l + 2;

    const int crow = tid >> 4;
    const int cc4  = tid & 15;

    {
        const float* kp = g_K + (t0 * 64) * DM + h * HD;
        const float* vp = g_Vt + (h * 64 + t0) * 4096;
        #pragma unroll
        for (int i = 0; i < 4; i++) {
            int rr = crow + 16 * i;
            cp16(&Ks[rr * KV_STRIDE + cc4 * 4], &kp[rr * DM + cc4 * 4]);
            cp16(&Vs[rr * KV_STRIDE + cc4 * 4], &vp[rr * 64 + cc4 * 4]);
        }
        cp_commit();
    }

    for (int t = t0; t < t1; t++) {
        if (t + 1 < t1) {
            int sn = (t + 1) & 1;
            const float* kp = g_K + ((t + 1) * 64) * DM + h * HD;
            const float* vp = g_Vt + (h * 64 + (t + 1)) * 4096;
            #pragma unroll
            for (int i = 0; i < 4; i++) {
                int rr = crow + 16 * i;
                cp16(&Ks[sn * KS_ELEMS + rr * KV_STRIDE + cc4 * 4], &kp[rr * DM + cc4 * 4]);
                cp16(&Vs[sn * VS_ELEMS + rr * KV_STRIDE + cc4 * 4], &vp[rr * 64 + cc4 * 4]);
            }
            cp_commit();
            cp_wait<1>();
        } else {
            cp_wait<0>();
        }
        __syncthreads();

        const float* ks = Ks + (t & 1) * KS_ELEMS;
        const float* vs = Vs + (t & 1) * VS_ELEMS;

        float sc4[8][4] = {};
        #pragma unroll
        for (int g = 0; g < 4; g++) {
            #pragma unroll
            for (int nt = 0; nt < 8; nt++) {
                float4 w = *(const float4*)&ks[(nt * 8 + gid) * KV_STRIDE + 16 * g + 4 * tig];
                mma8(sc4[nt], qa[2*g][0], qa[2*g][1], qa[2*g][2], qa[2*g][3],
                     __float_as_uint(w.x), __float_as_uint(w.y));
                mma8(sc4[nt], qa[2*g+1][0], qa[2*g+1][1], qa[2*g+1][2], qa[2*g+1][3],
                     __float_as_uint(w.z), __float_as_uint(w.w));
            }
        }

        if (t >= 2 * qt) {
            int ql0 = qt * QT_ROWS + warp * 16 + gid, ql1 = ql0 + 8;
            int kb0 = t * 64;
            #pragma unroll
            for (int nt = 0; nt < 8; nt++) {
                int kc = kb0 + nt * 8 + 2 * tig;
                if (kc     > ql0) sc4[nt][0] = -1e30f;
                if (kc + 1 > ql0) sc4[nt][1] = -1e30f;
                if (kc     > ql1) sc4[nt][2] = -1e30f;
                if (kc + 1 > ql1) sc4[nt][3] = -1e30f;
            }
        }

        float tm0 = -1e30f, tm1 = -1e30f;
        #pragma unroll
        for (int nt = 0; nt < 8; nt++) {
            tm0 = fmaxf(tm0, fmaxf(sc4[nt][0], sc4[nt][1]));
            tm1 = fmaxf(tm1, fmaxf(sc4[nt][2], sc4[nt][3]));
        }
        tm0 = fmaxf(tm0, __shfl_xor_sync(0xffffffffu, tm0, 1));
        tm0 = fmaxf(tm0, __shfl_xor_sync(0xffffffffu, tm0, 2));
        tm1 = fmaxf(tm1, __shfl_xor_sync(0xffffffffu, tm1, 1));
        tm1 = fmaxf(tm1, __shfl_xor_sync(0xffffffffu, tm1, 2));

        float mn0 = fmaxf(fmaxf(mr0, tm0), -1e28f);
        float mn1 = fmaxf(fmaxf(mr1, tm1), -1e28f);
        float rs0 = ex2(mr0 - mn0), rs1 = ex2(mr1 - mn1);
        mr0 = mn0; mr1 = mn1;

        uint32_t pu[8][4];
        float a0s = 0.f, a1s = 0.f;
        #pragma unroll
        for (int nt = 0; nt < 8; nt++) {
            float p0 = ex2(sc4[nt][0] - mn0);
            float p1 = ex2(sc4[nt][1] - mn0);
            float p2 = ex2(sc4[nt][2] - mn1);
            float p3 = ex2(sc4[nt][3] - mn1);
            a0s += p0 + p1; a1s += p2 + p3;
            pu[nt][0] = f2tf(p0); pu[nt][1] = f2tf(p1);
            pu[nt][2] = f2tf(p2); pu[nt][3] = f2tf(p3);
        }
        ls0 = ls0 * rs0 + a0s;
        ls1 = ls1 * rs1 + a1s;

        #pragma unroll
        for (int nt = 0; nt < 8; nt++) {
            o[nt][0] *= rs0; o[nt][1] *= rs0;
            o[nt][2] *= rs1; o[nt][3] *= rs1;
        }

        #pragma unroll
        for (int g = 0; g < 4; g++) {
            uint32_t A0[2], A1[2], A2[2], A3[2];
            #pragma unroll
            for (int qq = 0; qq < 2; qq++) {
                int kt = 2 * g + qq;
                uint32_t u0, u1, u2, u3;
                u0 = __shfl_sync(0xffffffffu, pu[kt][0], s0l);
                u1 = __shfl_sync(0xffffffffu, pu[kt][1], s0l);
                A0[qq] = (tig & 1) ? u1 : u0;
                u2 = __shfl_sync(0xffffffffu, pu[kt][2], s0l);
                u3 = __shfl_sync(0xffffffffu, pu[kt][3], s0l);
                A1[qq] = (tig & 1) ? u3 : u2;
                u0 = __shfl_sync(0xffffffffu, pu[kt][0], s2l);
                u1 = __shfl_sync(0xffffffffu, pu[kt][1], s2l);
                A2[qq] = (tig & 1) ? u1 : u0;
                u2 = __shfl_sync(0xffffffffu, pu[kt][2], s2l);
                u3 = __shfl_sync(0xffffffffu, pu[kt][3], s2l);
                A3[qq] = (tig & 1) ? u3 : u2;
            }
            #pragma unroll
            for (int nt = 0; nt < 8; nt++) {
                float4 w = *(const float4*)&vs[(nt * 8 + gid) * KV_STRIDE + 16 * g + 4 * tig];
                mma8(o[nt], A0[0], A1[0], A2[0], A3[0],
                     __float_as_uint(w.x), __float_as_uint(w.y));
                mma8(o[nt], A0[1], A1[1], A2[1], A3[1],
                     __float_as_uint(w.z), __float_as_uint(w.w));
            }
        }
        __syncthreads();
    }

    ls0 += __shfl_xor_sync(0xffffffffu, ls0, 1);
    ls0 += __shfl_xor_sync(0xffffffffu, ls0, 2);
    ls1 += __shfl_xor_sync(0xffffffffu, ls1, 1);
    ls1 += __shfl_xor_sync(0xffffffffu, ls1, 2);

    const int cid = (h * NQT + qt) * MAX_CH + ch;
    const int r0 = warp * 16 + gid, r1 = r0 + 8;
    float* Pop = g_Po[cid];
    #pragma unroll
    for (int nt = 0; nt < 8; nt++) {
        int c = nt * 8 + 2 * tig;
        *(float2*)&Pop[r0 * HD + c] = make_float2(o[nt][0], o[nt][1]);
        *(float2*)&Pop[r1 * HD + c] = make_float2(o[nt][2], o[nt][3]);
    }
    if (tig == 0) {
        g_Pm[cid][r0] = mr0; g_Pm[cid][r1] = mr1;
        g_Pl[cid][r0] = ls0; g_Pl[cid][r1] = ls1;
    }
}

// ---------------------------------------------------------------------------
// Split-K reduce (parallel): grid (NQT, NH, 4); each block = 32 rows,
// each thread = 1 row x 8 cols (two independent float4 chains per chunk).
// ---------------------------------------------------------------------------
__global__ __launch_bounds__(256) void attn_reduce()
{
    const int qt = blockIdx.x, h = blockIdx.y;
    const int nch = min(MAX_CH, (2 * qt + 2 + CHUNK_TILES - 1) / CHUNK_TILES);
    const int tid = threadIdx.x;
    const int row = blockIdx.z * 32 + (tid >> 3);   // 32 rows per block
    const int c0  = (tid & 7) * 8;                  // 8 cols per thread
    const int cidb = (h * NQT + qt) * MAX_CH;

    float m[MAX_CH], l[MAX_CH];
    float M = -1e30f;
    for (int c = 0; c < nch; c++) {
        m[c] = g_Pm[cidb + c][row];
        l[c] = g_Pl[cidb + c][row];
        M = fmaxf(M, m[c]);
    }
    float w[MAX_CH];
    float L = 0.f;
    for (int c = 0; c < nch; c++) {
        w[c] = ex2(m[c] - M);
        L += l[c] * w[c];
    }
    float inv = 1.f / L;

    float4 a0 = make_float4(0.f, 0.f, 0.f, 0.f);
    float4 a1 = make_float4(0.f, 0.f, 0.f, 0.f);
    for (int c = 0; c < nch; c++) {
        const float* p = &g_Po[cidb + c][row * HD + c0];
        float4 v0 = *(const float4*)&p[0];
        float4 v1 = *(const float4*)&p[4];
        float wc = w[c];
        a0.x += v0.x * wc; a0.y += v0.y * wc;
        a0.z += v0.z * wc; a0.w += v0.w * wc;
        a1.x += v1.x * wc; a1.y += v1.y * wc;
        a1.z += v1.z * wc; a1.w += v1.w * wc;
    }

    // g_O is perm16 on the k-dim: global col gc (mult of 4) -> base+{0,4,8,12}
    float* Orow = g_O + (qt * QT_ROWS + row) * DM;
    int gc = h * HD + c0;                 // multiple of 8
    int b0 = perm16(gc);
    int b1 = perm16(gc + 4);
    Orow[b0 +  0] = f2tf_f(a0.x * inv);
    Orow[b0 +  4] = f2tf_f(a0.y * inv);
    Orow[b0 +  8] = f2tf_f(a0.z * inv);
    Orow[b0 + 12] = f2tf_f(a0.w * inv);
    Orow[b1 +  0] = f2tf_f(a1.x * inv);
    Orow[b1 +  4] = f2tf_f(a1.y * inv);
    Orow[b1 +  8] = f2tf_f(a1.z * inv);
    Orow[b1 + 12] = f2tf_f(a1.w * inv);
}

// ---------------------------------------------------------------------------
// kernel_launch
// Input order: q, k, v, padding_mask, Wq, bq, Wk, bk, Wv, bv, Wo, bo
// ---------------------------------------------------------------------------
extern "C" void kernel_launch(void* const* d_in, const int* in_sizes, int n_in,
                              void* d_out, int out_size)
{
    (void)in_sizes; (void)n_in; (void)out_size;
    const float* q  = (const float*)d_in[0];
    const float* k  = (const float*)d_in[1];
    const float* v  = (const float*)d_in[2];
    const float* Wq = (const float*)d_in[4];
    const float* bq = (const float*)d_in[5];
    const float* Wk = (const float*)d_in[6];
    const float* bk = (const float*)d_in[7];
    const float* Wv = (const float*)d_in[8];
    const float* bv = (const float*)d_in[9];
    const float* Wo = (const float*)d_in[10];
    const float* bo = (const float*)d_in[11];
    float* out = (float*)d_out;

    float *qc, *kc, *vc, *wq, *wk, *wv, *wo;
    cudaGetSymbolAddress((void**)&qc, g_qc);
    cudaGetSymbolAddress((void**)&kc, g_kc);
    cudaGetSymbolAddress((void**)&vc, g_vc);
    cudaGetSymbolAddress((void**)&wq, g_Wq);
    cudaGetSymbolAddress((void**)&wk, g_Wk);
    cudaGetSymbolAddress((void**)&wv, g_Wv);
    cudaGetSymbolAddress((void**)&wo, g_Wo);

    static int smem_set = 0;
    if (!smem_set) {
        cudaFuncSetAttribute(attn_tc,
            cudaFuncAttributeMaxDynamicSharedMemorySize, ATTN_SMEM_BYTES);
        cudaFuncSetAttribute(proj_qkv,
            cudaFuncAttributeMaxDynamicSharedMemorySize, PROJ_SMEM_BYTES);
        cudaFuncSetAttribute(proj_out,
            cudaFuncAttributeMaxDynamicSharedMemorySize, PROJ_SMEM_BYTES);
        smem_set = 1;
    }

    const int n4i = SQ * DM / 4;      // 524288 -> 2048 blocks of 256
    dim3 pg(n4i / 256, 7);
    prep_all<<<pg, 256>>>(q, k, v, Wq, Wk, Wv, Wo,
                          qc, kc, vc, wq, wk, wv, wo);

    const float QSCALE = 0.125f * 1.4426950408889634f;
    dim3 pgrid(DM / 64, SQ / 64, 3);
    proj_qkv<<<pgrid, 128, PROJ_SMEM_BYTES>>>(bq, bk, bv, QSCALE);

    dim3 agrid(MAX_CH, NQT, NH);       // (8, 32, 8)
    attn_tc<<<agrid, 256, ATTN_SMEM_BYTES>>>();

    dim3 rgrid(NQT, NH, 4);            // (32, 8, 4) = 1024 CTAs
    attn_reduce<<<rgrid, 256>>>();

    dim3 ogrid(DM / 64, SQ / 64);
    proj_out<<<ogrid, 128, PROJ_SMEM_BYTES>>>(bo, out);
}